// round 9
// baseline (speedup 1.0000x reference)
#include <cuda_runtime.h>
#include <cuda_fp16.h>
#include <cstdint>

// Problem constants
#define NT    48
#define NE    48
#define BATCH 32
#define VS    512
#define M_ROWS (NT * BATCH)   // 1536 rows per z

// ---------------------------------------------------------------------------
// Device-global scratch (no allocations allowed)
// ---------------------------------------------------------------------------
__device__ float g_A[M_ROWS * VS];            // ta + b1, [t*32+b][h]
__device__ float g_E[M_ROWS * VS];            // eb,      [n*32+b][h]
__device__ __half g_Wh[2 * VS * VS];          // fp16 of W1 halves [z][h][v]

__device__ __forceinline__ uint32_t smem_u32(const void* p) {
    uint32_t a;
    asm("{ .reg .u64 t; cvta.to.shared.u64 t, %1; cvt.u32.u64 %0, t; }"
        : "=r"(a) : "l"(p));
    return a;
}

// ---------------------------------------------------------------------------
// Kernel 0: fp32 -> fp16 convert of W1 halves only (X converted in GEMM)
// ---------------------------------------------------------------------------
#define NW4 (2 * VS * VS / 4)       // 131072 float4 of W

__global__ __launch_bounds__(256) void wconv_kernel(const float* __restrict__ W1)
{
    const int gid = blockIdx.x * 256 + threadIdx.x;
    if (gid >= NW4) return;

    size_t e = (size_t)gid * 4;
    int z = (int)(e >> 18);              // / (VS*VS)
    size_t rem = e & ((1u << 18) - 1);
    int h = (int)(rem >> 9), v = (int)(rem & 511);
    float4 x = *(const float4*)(W1 + (size_t)h * (2 * VS) + z * VS + v);

    __half2 h01 = __floats2half2_rn(x.x, x.y);
    __half2 h23 = __floats2half2_rn(x.z, x.w);
    uint2 hp;
    hp.x = *(uint32_t*)&h01;
    hp.y = *(uint32_t*)&h23;
    *(uint2*)(g_Wh + e) = hp;
}

// ---------------------------------------------------------------------------
// Kernel 1: mma.sync fp16 GEMM; X converted fp32->fp16 in the load path.
// C[m,h] = sum_v fp16(X[m,v]) * fp16(W[h,v])  (+ b1[h] for z==0)
// CTA tile 128m x 128h, 8 warps, warp tile 64x32 (m16n8k16.f16).
// K chunks of 128: X via LDG.128 fp32 -> cvt -> STS (reg double buffer),
// W via cp.async fp16. Both smem tiles double-buffered, 272B padded rows.
// grid = (4 h, 12 m, 2 z), 256 threads.
// ---------------------------------------------------------------------------
#define NCHUNK 4                   // 4 chunks of K=128
#define ROW_B 272                  // 128 fp16 (256B) + 16B pad
#define TILE_B (128 * ROW_B)       // 34816 per tile
#define STAGE (2 * TILE_B)         // X + W = 69632
#define GEMM_SMEM (2 * STAGE)      // 139264

__device__ __forceinline__ void cp16(uint32_t dst, const void* src) {
    asm volatile("cp.async.cg.shared.global [%0], [%1], 16;"
                 :: "r"(dst), "l"(src));
}
__device__ __forceinline__ void ldsm4(uint32_t* f, uint32_t addr) {
    asm volatile("ldmatrix.sync.aligned.m8n8.x4.shared.b16 {%0,%1,%2,%3}, [%4];"
                 : "=r"(f[0]), "=r"(f[1]), "=r"(f[2]), "=r"(f[3]) : "r"(addr));
}
#define MMA_F16(acc, a, b0, b1)                                               \
    asm volatile(                                                             \
        "mma.sync.aligned.m16n8k16.row.col.f32.f16.f16.f32 "                  \
        "{%0,%1,%2,%3}, {%4,%5,%6,%7}, {%8,%9}, {%0,%1,%2,%3};"               \
        : "+f"((acc)[0]), "+f"((acc)[1]), "+f"((acc)[2]), "+f"((acc)[3])      \
        : "r"((a)[0]), "r"((a)[1]), "r"((a)[2]), "r"((a)[3]),                 \
          "r"(b0), "r"(b1))

__global__ __launch_bounds__(256) void mma_gemm_kernel(
    const float* __restrict__ Tg, const float* __restrict__ Eg,
    const float* __restrict__ b1)
{
    extern __shared__ char smem[];
    const uint32_t sbase = smem_u32(smem);
    const int tid  = threadIdx.x;
    const int lane = tid & 31;
    const int warp = tid >> 5;            // 0..7
    const int z  = blockIdx.z;
    const int m0 = blockIdx.y * 128;
    const int h0 = blockIdx.x * 128;
    float* __restrict__ C = z ? g_E : g_A;
    const float* __restrict__ Xf = z ? Eg : Tg;   // fp32 X rows [m][v]
    const __half* Wh = g_Wh + (size_t)z * VS * VS;

    const int wm0 = (warp & 1) * 64;       // warp m offset: {0,64}
    const int wn0 = (warp >> 1) * 32;      // warp h offset: {0,32,64,96}
    const int lg  = lane >> 2;             // group id 0..7
    const int lq  = lane & 3;              // quad id 0..3

    // ldmatrix per-lane base offsets (within a tile)
    const int m4 = lane >> 3;
    const int r8 = lane & 7;
    const uint32_t aOff = (uint32_t)((wm0 + (m4 & 1) * 8 + r8) * ROW_B + (m4 >> 1) * 16);
    const uint32_t bOff = (uint32_t)((wn0 + (m4 >> 1) * 8 + r8) * ROW_B + (m4 & 1) * 16);

    float acc[4][4][4];
#pragma unroll
    for (int mi = 0; mi < 4; mi++)
#pragma unroll
        for (int ni = 0; ni < 4; ni++)
#pragma unroll
            for (int r = 0; r < 4; r++) acc[mi][ni][r] = 0.f;

    // X load mapping: 128 rows x 32 float4 per chunk; 16 float4 per thread
    const int xrow = tid >> 5;             // base row step 8? no: id = i*256+tid
    const int xc16 = tid & 31;             // float4 col within row
    // (id = i*256 + tid -> row = id>>5 = i*8 + (tid>>5), col16 = tid&31)

    // W load mapping: 2048 int4 per tile, 8 per thread
    const int lrow = tid >> 4;             // 0..15
    const int lcol = tid & 15;             // int4 within 256B row

    float4 rx[16];                         // fp32 X prefetch (chunk c+1)

    auto prefetchX = [&](int c) {
        const int k0 = c * 128;
#pragma unroll
        for (int i = 0; i < 16; i++) {
            const int row = i * 8 + xrow;
            rx[i] = *(const float4*)(Xf + (size_t)(m0 + row) * VS + k0 + xc16 * 4);
        }
    };

    auto storeX = [&](int c) {
        char* bufX = smem + (c & 1) * STAGE;
#pragma unroll
        for (int i = 0; i < 16; i++) {
            const int row = i * 8 + xrow;
            __half2 h01 = __floats2half2_rn(rx[i].x, rx[i].y);
            __half2 h23 = __floats2half2_rn(rx[i].z, rx[i].w);
            uint2 hp;
            hp.x = *(uint32_t*)&h01;
            hp.y = *(uint32_t*)&h23;
            *(uint2*)(bufX + row * ROW_B + xc16 * 8) = hp;
        }
    };

    auto issueW = [&](int c) {
        const int k0 = c * 128;
        const uint32_t sW = sbase + (c & 1) * STAGE + TILE_B;
#pragma unroll
        for (int i = 0; i < 8; i++) {
            const int row = i * 16 + lrow;
            cp16(sW + (uint32_t)(row * ROW_B + lcol * 16),
                 Wh + (size_t)(h0 + row) * VS + k0 + lcol * 8);
        }
        asm volatile("cp.async.commit_group;");
    };

    auto compute = [&](int c) {
        const uint32_t s0 = sbase + (c & 1) * STAGE;
        const uint32_t sA = s0 + aOff;
        const uint32_t sB = s0 + TILE_B + bOff;
#pragma unroll
        for (int kc = 0; kc < 8; kc++) {
            uint32_t bf[2][4];
            ldsm4(bf[0], sB + kc * 32);
            ldsm4(bf[1], sB + 16 * ROW_B + kc * 32);
#pragma unroll
            for (int mi = 0; mi < 4; mi++) {
                uint32_t a[4];
                ldsm4(a, sA + mi * 16 * ROW_B + kc * 32);
#pragma unroll
                for (int ni = 0; ni < 4; ni++)
                    MMA_F16(acc[mi][ni], a,
                            bf[ni >> 1][(ni & 1) * 2], bf[ni >> 1][(ni & 1) * 2 + 1]);
            }
        }
    };

    // Prologue: chunk0 into buffer0, chunk1 prefetched to regs / cp.async
    prefetchX(0);
    issueW(0);
    storeX(0);
    prefetchX(1);          // regs now hold chunk 1
    issueW(1);
    asm volatile("cp.async.wait_group 1;");   // W chunk0 done
    __syncthreads();                           // X chunk0 stores visible

    for (int c = 0; c < NCHUNK; c++) {
        compute(c);
        __syncthreads();   // all warps done reading buffers of chunk c
        if (c + 1 < NCHUNK) {
            storeX(c + 1);                     // regs (chunk c+1) -> other buffer
            if (c + 2 < NCHUNK) {
                prefetchX(c + 2);              // regs <- chunk c+2 (hidden by next compute)
                issueW(c + 2);
            }
            if (c + 2 < NCHUNK)
                asm volatile("cp.async.wait_group 1;");  // W chunk c+1 done
            else
                asm volatile("cp.async.wait_group 0;");
            __syncthreads();                   // storeX(c+1) visible
        }
    }

    // Epilogue: bias (z==0) + float2 stores
#pragma unroll
    for (int mi = 0; mi < 4; mi++) {
        const int m = m0 + wm0 + mi * 16 + lg;
#pragma unroll
        for (int ni = 0; ni < 4; ni++) {
            const int h = h0 + wn0 + ni * 8 + lq * 2;
            float2 bias = make_float2(0.f, 0.f);
            if (z == 0) bias = *(const float2*)(b1 + h);
            float2 v0 = make_float2(acc[mi][ni][0] + bias.x, acc[mi][ni][1] + bias.y);
            float2 v1 = make_float2(acc[mi][ni][2] + bias.x, acc[mi][ni][3] + bias.y);
            *(float2*)(C + (size_t)m * VS + h)       = v0;
            *(float2*)(C + (size_t)(m + 8) * VS + h) = v1;
        }
    }
}

// ---------------------------------------------------------------------------
// Kernel 2: out[t,n,b] = sum_h w2[h]*tanh(A[t,b,h]+E[n,b,h]) + b2
// Block = (4 targets, b). 256 threads, E from L2, 16 MUFU chains per e-load.
// ---------------------------------------------------------------------------
#define TPB 4

__device__ __forceinline__ float tanh_fast(float x) {
    float y;
    asm("tanh.approx.f32 %0, %1;" : "=f"(y) : "f"(x));
    return y;
}

__global__ __launch_bounds__(256) void fuse_kernel(
    const float* __restrict__ W2, const float* __restrict__ b2,
    float* __restrict__ out)
{
    const int bb = blockIdx.y;
    const int t0 = blockIdx.x * TPB;
    const int warp = threadIdx.x >> 5;
    const int lane = threadIdx.x & 31;

    const float4* W4 = (const float4*)W2;
    float4 w[4];
#pragma unroll
    for (int j = 0; j < 4; j++) w[j] = __ldg(&W4[lane + 32 * j]);

    float4 a[TPB][4];
#pragma unroll
    for (int t = 0; t < TPB; t++) {
        const float4* A4 = (const float4*)(g_A + ((size_t)((t0 + t) * BATCH + bb)) * VS);
#pragma unroll
        for (int j = 0; j < 4; j++) a[t][j] = A4[lane + 32 * j];
    }
    const float b2v = __ldg(b2);

    for (int n = warp; n < NE; n += 8) {
        const float4* E4 = (const float4*)(g_E + ((size_t)(n * BATCH + bb)) * VS);
        float s[TPB] = {0.f, 0.f, 0.f, 0.f};
#pragma unroll
        for (int j = 0; j < 4; j++) {
            float4 e = __ldg(&E4[lane + 32 * j]);
#pragma unroll
            for (int t = 0; t < TPB; t++) {
                s[t] = fmaf(w[j].x, tanh_fast(a[t][j].x + e.x), s[t]);
                s[t] = fmaf(w[j].y, tanh_fast(a[t][j].y + e.y), s[t]);
                s[t] = fmaf(w[j].z, tanh_fast(a[t][j].z + e.z), s[t]);
                s[t] = fmaf(w[j].w, tanh_fast(a[t][j].w + e.w), s[t]);
            }
        }
#pragma unroll
        for (int off = 16; off; off >>= 1)
#pragma unroll
            for (int t = 0; t < TPB; t++)
                s[t] += __shfl_xor_sync(0xffffffffu, s[t], off);
        if (lane == 0) {
#pragma unroll
            for (int t = 0; t < TPB; t++)
                out[((size_t)(t0 + t) * NE + n) * BATCH + bb] = s[t] + b2v;
        }
    }
}

// ---------------------------------------------------------------------------
// Launch: inputs in metadata order: targets, embeddings, W1, b1, W2, b2
// ---------------------------------------------------------------------------
extern "C" void kernel_launch(void* const* d_in, const int* in_sizes, int n_in,
                              void* d_out, int out_size)
{
    const float* targets    = (const float*)d_in[0];
    const float* embeddings = (const float*)d_in[1];
    const float* W1         = (const float*)d_in[2];
    const float* b1         = (const float*)d_in[3];
    const float* W2         = (const float*)d_in[4];
    const float* b2         = (const float*)d_in[5];
    float* out = (float*)d_out;

    cudaFuncSetAttribute(mma_gemm_kernel,
                         cudaFuncAttributeMaxDynamicSharedMemorySize, GEMM_SMEM);

    wconv_kernel<<<(NW4 + 255) / 256, 256>>>(W1);   // 512 blocks

    dim3 gg(4, 12, 2);   // h-tiles, m-tiles, z
    mma_gemm_kernel<<<gg, 256, GEMM_SMEM>>>(targets, embeddings, b1);

    dim3 gf(NT / TPB, BATCH);   // 12 x 32
    fuse_kernel<<<gf, 256>>>(W2, b2, out);
}

// round 10
// speedup vs baseline: 1.0121x; 1.0121x over previous
#include <cuda_runtime.h>
#include <cuda_fp16.h>
#include <cstdint>

// Problem constants
#define NT    48
#define NE    48
#define BATCH 32
#define VS    512
#define M_ROWS (NT * BATCH)   // 1536 rows per z

// ---------------------------------------------------------------------------
// Device-global scratch (no allocations allowed)
// ---------------------------------------------------------------------------
__device__ __half g_A[M_ROWS * VS];           // fp16(ta + b1), [t*32+b][h]
__device__ __half g_E[M_ROWS * VS];           // fp16(eb),      [n*32+b][h]
__device__ __half g_Wh[2 * VS * VS];          // fp16 of W1 halves [z][h][v]

__device__ __forceinline__ uint32_t smem_u32(const void* p) {
    uint32_t a;
    asm("{ .reg .u64 t; cvta.to.shared.u64 t, %1; cvt.u32.u64 %0, t; }"
        : "=r"(a) : "l"(p));
    return a;
}

// ---------------------------------------------------------------------------
// Kernel 0: fp32 -> fp16 convert of W1 halves. Batched loads (MLP=4).
// ---------------------------------------------------------------------------
#define NW4 (2 * VS * VS / 4)       // 131072 float4 of W
#define WCONV_BLOCKS 128            // 128*256*4 = 131072

__global__ __launch_bounds__(256) void wconv_kernel(const float* __restrict__ W1)
{
    const int gid = blockIdx.x * 256 + threadIdx.x;

    float4 v[4];
#pragma unroll
    for (int i = 0; i < 4; i++) {
        const int idx = gid + i * 32768;
        size_t e = (size_t)idx * 4;
        int z = (int)(e >> 18);
        size_t rem = e & ((1u << 18) - 1);
        int h = (int)(rem >> 9), vv = (int)(rem & 511);
        v[i] = *(const float4*)(W1 + (size_t)h * (2 * VS) + z * VS + vv);
    }
#pragma unroll
    for (int i = 0; i < 4; i++) {
        const int idx = gid + i * 32768;
        size_t e = (size_t)idx * 4;
        __half2 h01 = __floats2half2_rn(v[i].x, v[i].y);
        __half2 h23 = __floats2half2_rn(v[i].z, v[i].w);
        uint2 hp;
        hp.x = *(uint32_t*)&h01;
        hp.y = *(uint32_t*)&h23;
        *(uint2*)(g_Wh + e) = hp;
    }
}

// ---------------------------------------------------------------------------
// Kernel 1: mma.sync fp16 GEMM; X converted fp32->fp16 in the load path.
// C[m,h] = fp16( sum_v fp16(X[m,v]) * fp16(W[h,v]) + b1[h] )
// CTA tile 128m x 128h, 8 warps, warp tile 64x32 (m16n8k16.f16).
// grid = (4 h, 12 m, 2 z), 256 threads. Output stored as fp16.
// ---------------------------------------------------------------------------
#define NCHUNK 4                   // 4 chunks of K=128
#define ROW_B 272                  // 128 fp16 (256B) + 16B pad
#define TILE_B (128 * ROW_B)       // 34816 per tile
#define STAGE (2 * TILE_B)         // X + W = 69632
#define GEMM_SMEM (2 * STAGE)      // 139264

__device__ __forceinline__ void cp16(uint32_t dst, const void* src) {
    asm volatile("cp.async.cg.shared.global [%0], [%1], 16;"
                 :: "r"(dst), "l"(src));
}
__device__ __forceinline__ void ldsm4(uint32_t* f, uint32_t addr) {
    asm volatile("ldmatrix.sync.aligned.m8n8.x4.shared.b16 {%0,%1,%2,%3}, [%4];"
                 : "=r"(f[0]), "=r"(f[1]), "=r"(f[2]), "=r"(f[3]) : "r"(addr));
}
#define MMA_F16(acc, a, b0, b1)                                               \
    asm volatile(                                                             \
        "mma.sync.aligned.m16n8k16.row.col.f32.f16.f16.f32 "                  \
        "{%0,%1,%2,%3}, {%4,%5,%6,%7}, {%8,%9}, {%0,%1,%2,%3};"               \
        : "+f"((acc)[0]), "+f"((acc)[1]), "+f"((acc)[2]), "+f"((acc)[3])      \
        : "r"((a)[0]), "r"((a)[1]), "r"((a)[2]), "r"((a)[3]),                 \
          "r"(b0), "r"(b1))

__global__ __launch_bounds__(256) void mma_gemm_kernel(
    const float* __restrict__ Tg, const float* __restrict__ Eg,
    const float* __restrict__ b1)
{
    extern __shared__ char smem[];
    const uint32_t sbase = smem_u32(smem);
    const int tid  = threadIdx.x;
    const int lane = tid & 31;
    const int warp = tid >> 5;            // 0..7
    const int z  = blockIdx.z;
    const int m0 = blockIdx.y * 128;
    const int h0 = blockIdx.x * 128;
    __half* __restrict__ C = z ? g_E : g_A;
    const float* __restrict__ Xf = z ? Eg : Tg;   // fp32 X rows [m][v]
    const __half* Wh = g_Wh + (size_t)z * VS * VS;

    const int wm0 = (warp & 1) * 64;       // warp m offset: {0,64}
    const int wn0 = (warp >> 1) * 32;      // warp h offset: {0,32,64,96}
    const int lg  = lane >> 2;             // group id 0..7
    const int lq  = lane & 3;              // quad id 0..3

    // ldmatrix per-lane base offsets (within a tile)
    const int m4 = lane >> 3;
    const int r8 = lane & 7;
    const uint32_t aOff = (uint32_t)((wm0 + (m4 & 1) * 8 + r8) * ROW_B + (m4 >> 1) * 16);
    const uint32_t bOff = (uint32_t)((wn0 + (m4 >> 1) * 8 + r8) * ROW_B + (m4 & 1) * 16);

    float acc[4][4][4];
#pragma unroll
    for (int mi = 0; mi < 4; mi++)
#pragma unroll
        for (int ni = 0; ni < 4; ni++)
#pragma unroll
            for (int r = 0; r < 4; r++) acc[mi][ni][r] = 0.f;

    // X load mapping: id = i*256 + tid -> row = id>>5, float4 col = tid&31
    const int xrow = tid >> 5;
    const int xc16 = tid & 31;

    // W load mapping: 2048 int4 per tile, 8 per thread
    const int lrow = tid >> 4;             // 0..15
    const int lcol = tid & 15;             // int4 within 256B row

    float4 rx[16];                         // fp32 X prefetch

    auto prefetchX = [&](int c) {
        const int k0 = c * 128;
#pragma unroll
        for (int i = 0; i < 16; i++) {
            const int row = i * 8 + xrow;
            rx[i] = *(const float4*)(Xf + (size_t)(m0 + row) * VS + k0 + xc16 * 4);
        }
    };

    auto storeX = [&](int c) {
        char* bufX = smem + (c & 1) * STAGE;
#pragma unroll
        for (int i = 0; i < 16; i++) {
            const int row = i * 8 + xrow;
            __half2 h01 = __floats2half2_rn(rx[i].x, rx[i].y);
            __half2 h23 = __floats2half2_rn(rx[i].z, rx[i].w);
            uint2 hp;
            hp.x = *(uint32_t*)&h01;
            hp.y = *(uint32_t*)&h23;
            *(uint2*)(bufX + row * ROW_B + xc16 * 8) = hp;
        }
    };

    auto issueW = [&](int c) {
        const int k0 = c * 128;
        const uint32_t sW = sbase + (c & 1) * STAGE + TILE_B;
#pragma unroll
        for (int i = 0; i < 8; i++) {
            const int row = i * 16 + lrow;
            cp16(sW + (uint32_t)(row * ROW_B + lcol * 16),
                 Wh + (size_t)(h0 + row) * VS + k0 + lcol * 8);
        }
        asm volatile("cp.async.commit_group;");
    };

    auto compute = [&](int c) {
        const uint32_t s0 = sbase + (c & 1) * STAGE;
        const uint32_t sA = s0 + aOff;
        const uint32_t sB = s0 + TILE_B + bOff;
#pragma unroll
        for (int kc = 0; kc < 8; kc++) {
            uint32_t bf[2][4];
            ldsm4(bf[0], sB + kc * 32);
            ldsm4(bf[1], sB + 16 * ROW_B + kc * 32);
#pragma unroll
            for (int mi = 0; mi < 4; mi++) {
                uint32_t a[4];
                ldsm4(a, sA + mi * 16 * ROW_B + kc * 32);
#pragma unroll
                for (int ni = 0; ni < 4; ni++)
                    MMA_F16(acc[mi][ni], a,
                            bf[ni >> 1][(ni & 1) * 2], bf[ni >> 1][(ni & 1) * 2 + 1]);
            }
        }
    };

    // Prologue
    prefetchX(0);
    issueW(0);
    storeX(0);
    prefetchX(1);
    issueW(1);
    asm volatile("cp.async.wait_group 1;");
    __syncthreads();

    for (int c = 0; c < NCHUNK; c++) {
        compute(c);
        __syncthreads();
        if (c + 1 < NCHUNK) {
            storeX(c + 1);
            if (c + 2 < NCHUNK) {
                prefetchX(c + 2);
                issueW(c + 2);
                asm volatile("cp.async.wait_group 1;");
            } else {
                asm volatile("cp.async.wait_group 0;");
            }
            __syncthreads();
        }
    }

    // Epilogue: bias (z==0), convert to fp16, packed 4-byte stores
#pragma unroll
    for (int mi = 0; mi < 4; mi++) {
        const int m = m0 + wm0 + mi * 16 + lg;
#pragma unroll
        for (int ni = 0; ni < 4; ni++) {
            const int h = h0 + wn0 + ni * 8 + lq * 2;
            float2 bias = make_float2(0.f, 0.f);
            if (z == 0) bias = *(const float2*)(b1 + h);
            __half2 v0 = __floats2half2_rn(acc[mi][ni][0] + bias.x,
                                           acc[mi][ni][1] + bias.y);
            __half2 v1 = __floats2half2_rn(acc[mi][ni][2] + bias.x,
                                           acc[mi][ni][3] + bias.y);
            *(uint32_t*)(C + (size_t)m * VS + h)       = *(uint32_t*)&v0;
            *(uint32_t*)(C + (size_t)(m + 8) * VS + h) = *(uint32_t*)&v1;
        }
    }
}

// ---------------------------------------------------------------------------
// Kernel 2: out[t,n,b] = sum_h w2[h]*tanh(A[t,b,h]+E[n,b,h]) + b2
// fp16x2 pipeline: HADD2 -> tanh.approx.f16x2 -> cvt -> fp32 FFMA accum.
// Block = (4 targets, b). 256 threads.
// ---------------------------------------------------------------------------
#define TPB 4

__device__ __forceinline__ uint32_t hadd2u(uint32_t a, uint32_t b) {
    uint32_t r;
    asm("add.f16x2 %0, %1, %2;" : "=r"(r) : "r"(a), "r"(b));
    return r;
}
__device__ __forceinline__ uint32_t tanh2u(uint32_t x) {
    uint32_t y;
    asm("tanh.approx.f16x2 %0, %1;" : "=r"(y) : "r"(x));
    return y;
}
__device__ __forceinline__ float2 h2f2(uint32_t x) {
    __half2 h = *(__half2*)&x;
    return __half22float2(h);
}

__global__ __launch_bounds__(256) void fuse_kernel(
    const float* __restrict__ W2, const float* __restrict__ b2,
    float* __restrict__ out)
{
    const int bb = blockIdx.y;
    const int t0 = blockIdx.x * TPB;
    const int warp = threadIdx.x >> 5;
    const int lane = threadIdx.x & 31;

    // lane covers h in [8*lane, 8*lane+8) and [8*(lane+32), 8*(lane+32)+8)
    const float4* W4 = (const float4*)W2;
    float4 w0 = __ldg(&W4[2 * lane]);
    float4 w1 = __ldg(&W4[2 * lane + 1]);
    float4 w2v = __ldg(&W4[2 * lane + 64]);
    float4 w3 = __ldg(&W4[2 * lane + 65]);

    uint4 a0[TPB], a1[TPB];
#pragma unroll
    for (int t = 0; t < TPB; t++) {
        const uint4* A4 = (const uint4*)(g_A + ((size_t)((t0 + t) * BATCH + bb)) * VS);
        a0[t] = A4[lane];
        a1[t] = A4[lane + 32];
    }
    const float b2v = __ldg(b2);

    for (int n = warp; n < NE; n += 8) {
        const uint4* E4 = (const uint4*)(g_E + ((size_t)(n * BATCH + bb)) * VS);
        uint4 e0 = __ldg(&E4[lane]);
        uint4 e1 = __ldg(&E4[lane + 32]);

        float s[TPB] = {0.f, 0.f, 0.f, 0.f};
#pragma unroll
        for (int t = 0; t < TPB; t++) {
            // first 8 halves: weights w0 (4) + w1 (4)
            float2 f;
            f = h2f2(tanh2u(hadd2u(a0[t].x, e0.x)));
            s[t] = fmaf(w0.x, f.x, s[t]); s[t] = fmaf(w0.y, f.y, s[t]);
            f = h2f2(tanh2u(hadd2u(a0[t].y, e0.y)));
            s[t] = fmaf(w0.z, f.x, s[t]); s[t] = fmaf(w0.w, f.y, s[t]);
            f = h2f2(tanh2u(hadd2u(a0[t].z, e0.z)));
            s[t] = fmaf(w1.x, f.x, s[t]); s[t] = fmaf(w1.y, f.y, s[t]);
            f = h2f2(tanh2u(hadd2u(a0[t].w, e0.w)));
            s[t] = fmaf(w1.z, f.x, s[t]); s[t] = fmaf(w1.w, f.y, s[t]);
            // second 8 halves: weights w2v (4) + w3 (4)
            f = h2f2(tanh2u(hadd2u(a1[t].x, e1.x)));
            s[t] = fmaf(w2v.x, f.x, s[t]); s[t] = fmaf(w2v.y, f.y, s[t]);
            f = h2f2(tanh2u(hadd2u(a1[t].y, e1.y)));
            s[t] = fmaf(w2v.z, f.x, s[t]); s[t] = fmaf(w2v.w, f.y, s[t]);
            f = h2f2(tanh2u(hadd2u(a1[t].z, e1.z)));
            s[t] = fmaf(w3.x, f.x, s[t]); s[t] = fmaf(w3.y, f.y, s[t]);
            f = h2f2(tanh2u(hadd2u(a1[t].w, e1.w)));
            s[t] = fmaf(w3.z, f.x, s[t]); s[t] = fmaf(w3.w, f.y, s[t]);
        }
#pragma unroll
        for (int off = 16; off; off >>= 1)
#pragma unroll
            for (int t = 0; t < TPB; t++)
                s[t] += __shfl_xor_sync(0xffffffffu, s[t], off);
        if (lane == 0) {
#pragma unroll
            for (int t = 0; t < TPB; t++)
                out[((size_t)(t0 + t) * NE + n) * BATCH + bb] = s[t] + b2v;
        }
    }
}

// ---------------------------------------------------------------------------
// Launch: inputs in metadata order: targets, embeddings, W1, b1, W2, b2
// ---------------------------------------------------------------------------
extern "C" void kernel_launch(void* const* d_in, const int* in_sizes, int n_in,
                              void* d_out, int out_size)
{
    const float* targets    = (const float*)d_in[0];
    const float* embeddings = (const float*)d_in[1];
    const float* W1         = (const float*)d_in[2];
    const float* b1         = (const float*)d_in[3];
    const float* W2         = (const float*)d_in[4];
    const float* b2         = (const float*)d_in[5];
    float* out = (float*)d_out;

    cudaFuncSetAttribute(mma_gemm_kernel,
                         cudaFuncAttributeMaxDynamicSharedMemorySize, GEMM_SMEM);

    wconv_kernel<<<WCONV_BLOCKS, 256>>>(W1);

    dim3 gg(4, 12, 2);   // h-tiles, m-tiles, z
    mma_gemm_kernel<<<gg, 256, GEMM_SMEM>>>(targets, embeddings, b1);

    dim3 gf(NT / TPB, BATCH);   // 12 x 32
    fuse_kernel<<<gf, 256>>>(W2, b2, out);
}